// round 3
// baseline (speedup 1.0000x reference)
#include <cuda_runtime.h>
#include <math.h>

#ifndef M_PI
#define M_PI 3.14159265358979323846
#endif

#define MROWS 4096
#define ROWSTRIDE 74
#define FULLMASK 0xffffffffu

__device__ double g_acc[6];        // 0: pairsum, 1: rec, 2: ce, 3: den, 4: B
__device__ float2 g_zs[MROWS];     // z prescaled by 1/sqrt(4*gamma)

// large-branch poly coefficients folded with sqrt(2)*7.5^k
#define SQ2 1.4142135623730951
__device__ __constant__ float QD[9] = {
    (float)(0.39894228 * SQ2),
    (float)(0.01328592 * SQ2 * 7.5),
    (float)(0.00225319 * SQ2 * 56.25),
    (float)(-0.00157565 * SQ2 * 421.875),
    (float)(0.0091628 * SQ2 * 3164.0625),
    (float)(-0.02057706 * SQ2 * 23730.46875),
    (float)(0.02635537 * SQ2 * 177978.515625),
    (float)(-0.01647633 * SQ2 * 1334838.8671875),
    (float)(0.00392377 * SQ2 * 10011291.50390625)
};

// phi(x) = (x<=7.5) ? P6((x/7.5)^2)*exp(-x/2) + K1 : rsqrt(x)*Q8(1/x)
__device__ __forceinline__ float phi_sel(float x, float K1) {
    float t  = x * 0.13333333333333333f;
    float t2 = t * t;
    float p = fmaf(t2, 0.0045813f, 0.0360768f);
    p = fmaf(t2, p, 0.2659732f);
    p = fmaf(t2, p, 1.2067492f);
    p = fmaf(t2, p, 3.0899424f);
    p = fmaf(t2, p, 3.5156229f);
    p = fmaf(t2, p, 1.0f);
    float e  = __expf(-0.5f * x);
    float sv = fmaf(p, e, K1);

    float r  = rsqrtf(x);
    float iv = r * r;
    float q = fmaf(iv, QD[8], QD[7]);
    q = fmaf(iv, q, QD[6]);
    q = fmaf(iv, q, QD[5]);
    q = fmaf(iv, q, QD[4]);
    q = fmaf(iv, q, QD[3]);
    q = fmaf(iv, q, QD[2]);
    q = fmaf(iv, q, QD[1]);
    q = fmaf(iv, q, QD[0]);
    float bv = r * q;
    return (x <= 7.5f) ? sv : bv;
}

__device__ __forceinline__ float ftanh(float x) {
    float e = __expf(2.f * x);
    return 1.f - __fdividef(2.f, e + 1.f);
}

__device__ __forceinline__ float wsum(float v) {
    #pragma unroll
    for (int o = 16; o; o >>= 1) v += __shfl_xor_sync(FULLMASK, v, o);
    return v;
}
__device__ __forceinline__ float wmax(float v) {
    #pragma unroll
    for (int o = 16; o; o >>= 1) v = fmaxf(v, __shfl_xor_sync(FULLMASK, v, o));
    return v;
}

__global__ void k_zero() { if (threadIdx.x < 6) g_acc[threadIdx.x] = 0.0; }

// ---------------- rows kernel: MLP + rec + class + B, writes prescaled z ----
__global__ void __launch_bounds__(256) k_rows(
    const float* __restrict__ bd,
    const float* __restrict__ We1, const float* __restrict__ be1,
    const float* __restrict__ We2, const float* __restrict__ be2,
    const float* __restrict__ We3, const float* __restrict__ be3,
    const float* __restrict__ Wd1, const float* __restrict__ bd1,
    const float* __restrict__ Wd2, const float* __restrict__ bd2,
    const float* __restrict__ Wd3, const float* __restrict__ bd3,
    const float* __restrict__ means, const float* __restrict__ vars,
    const float* __restrict__ probs,
    float K1, float rsc, float gam)
{
    __shared__ float sWe1[2048], sWe2[512], sWe3[32], sWd1[32], sWd2[512], sWd3[2048];
    __shared__ float sBe1[32], sBe2[16], sBe3[2], sBd1[16], sBd2[32], sBd3[64];
    __shared__ float sClsC[10], sInv2v[10], sBcoef[10], sBinv[10], sMu[20];
    __shared__ float stau[8][64], sh1[8][32], sh2[8][16], sd1[8][16], sd2[8][32];
    __shared__ double sRed[8][4];

    const int tid  = threadIdx.x;
    const int w    = tid >> 5;
    const int l    = tid & 31;

    for (int i = tid; i < 2048; i += 256) { sWe1[i] = We1[i]; sWd3[i] = Wd3[i]; }
    for (int i = tid; i < 512;  i += 256) { sWe2[i] = We2[i]; sWd2[i] = Wd2[i]; }
    if (tid < 32) { sWe3[tid] = We3[tid]; sWd1[tid] = Wd1[tid]; sBe1[tid] = be1[tid]; sBd2[tid] = bd2[tid]; }
    if (tid < 16) { sBe2[tid] = be2[tid]; sBd1[tid] = bd1[tid]; }
    if (tid < 2)  { sBe3[tid] = be3[tid]; }
    if (tid < 64) { sBd3[tid] = bd3[tid]; }
    if (tid < 20) sMu[tid] = means[tid];
    if (tid < 10) {
        float v = vars[tid], p = probs[tid];
        sClsC[tid]  = logf(p) - logf(2.f * (float)M_PI * v);
        sInv2v[tid] = 0.5f / v;
        float vp2g = v + 2.f * gam;
        sBcoef[tid] = 2.f * p / ((float)MROWS * sqrtf(2.f * (float)M_PI * vp2g));
        sBinv[tid]  = 0.5f / vp2g;
    }
    __syncthreads();

    float rec_acc = 0.f, ce_acc = 0.f, b_acc = 0.f, den_acc = 0.f;

    const int rowBase = blockIdx.x * 32 + w * 4;
    for (int r = 0; r < 4; r++) {
        int row = rowBase + r;
        const float* rowp = bd + row * ROWSTRIDE;
        float t0 = rowp[l];
        float t1 = rowp[32 + l];
        float lab = (l < 10) ? rowp[64 + l] : 0.f;
        stau[w][l] = t0; stau[w][32 + l] = t1;
        __syncwarp();

        float a1 = sBe1[l];
        #pragma unroll 16
        for (int k = 0; k < 64; k++) a1 = fmaf(stau[w][k], sWe1[k * 32 + l], a1);
        sh1[w][l] = ftanh(a1);
        __syncwarp();

        int j16 = l & 15;
        float a2 = sBe2[j16];
        #pragma unroll 8
        for (int k = 0; k < 32; k++) a2 = fmaf(sh1[w][k], sWe2[k * 16 + j16], a2);
        if (l < 16) sh2[w][l] = ftanh(a2);
        __syncwarp();

        int j2 = l & 1;
        float a3 = sBe3[j2];
        #pragma unroll
        for (int k = 0; k < 16; k++) a3 = fmaf(sh2[w][k], sWe3[k * 2 + j2], a3);
        float z0 = __shfl_sync(FULLMASK, a3, 0);
        float z1 = __shfl_sync(FULLMASK, a3, 1);
        if (l == 0) g_zs[row] = make_float2(z0 * rsc, z1 * rsc);

        float ad1 = sBd1[j16] + z0 * sWd1[j16] + z1 * sWd1[16 + j16];
        if (l < 16) sd1[w][l] = ftanh(ad1);
        __syncwarp();

        float ad2 = sBd2[l];
        #pragma unroll
        for (int k = 0; k < 16; k++) ad2 = fmaf(sd1[w][k], sWd2[k * 32 + l], ad2);
        sd2[w][l] = ftanh(ad2);
        __syncwarp();

        float o0 = sBd3[l], o1 = sBd3[32 + l];
        #pragma unroll 8
        for (int k = 0; k < 32; k++) {
            float dk = sd2[w][k];
            o0 = fmaf(dk, sWd3[k * 64 + l], o0);
            o1 = fmaf(dk, sWd3[k * 64 + 32 + l], o1);
        }
        float e0 = t0 - o0, e1 = t1 - o1;
        rec_acc += e0 * e0 + e1 * e1;

        // class + B (lanes 0..9 active, others masked)
        int j = (l < 10) ? l : 0;
        float dz0 = z0 - sMu[2 * j], dz1 = z1 - sMu[2 * j + 1];
        float sq = dz0 * dz0 + dz1 * dz1;
        float logit = sClsC[j] - sq * sInv2v[j];
        float lm = (l < 10) ? logit : -1e30f;
        float mx = wmax(lm);
        float ex = (l < 10) ? __expf(logit - mx) : 0.f;
        float Z = wsum(ex);
        float lsm = logit - mx - __logf(Z);
        float labsum = wsum(lab);
        float maskf = (labsum == 1.0f) ? 1.f : 0.f;
        ce_acc += (l < 10) ? (-lab * lsm * maskf) : 0.f;
        if (l == 0) den_acc += labsum;
        b_acc += (l < 10) ? sBcoef[j] * phi_sel(sq * sBinv[j], K1) : 0.f;
    }

    rec_acc = wsum(rec_acc);
    ce_acc  = wsum(ce_acc);
    b_acc   = wsum(b_acc);
    den_acc = wsum(den_acc);
    if (l == 0) {
        sRed[w][0] = (double)rec_acc; sRed[w][1] = (double)ce_acc;
        sRed[w][2] = (double)b_acc;   sRed[w][3] = (double)den_acc;
    }
    __syncthreads();
    if (tid == 0) {
        double r0 = 0, r1 = 0, r2 = 0, r3 = 0;
        for (int i = 0; i < 8; i++) { r0 += sRed[i][0]; r1 += sRed[i][1]; r2 += sRed[i][2]; r3 += sRed[i][3]; }
        atomicAdd(&g_acc[1], r0); atomicAdd(&g_acc[2], r1);
        atomicAdd(&g_acc[4], r2); atomicAdd(&g_acc[3], r3);
    }
}

// ---------------- pairs kernel: A-term over 64x64 tiles ----------------
__global__ void __launch_bounds__(256) k_pairs(float K1) {
    __shared__ float2 zi[64], zj[64];
    __shared__ double sRed[8];

    int t = blockIdx.x;
    int ci = 0, rem = t;
    for (;;) { int rl = 64 - ci; if (rem < rl) break; rem -= rl; ci++; }
    int cj = ci + rem;

    int tid = threadIdx.x;
    if (tid < 64) zi[tid] = g_zs[ci * 64 + tid];
    else if (tid < 128) zj[tid - 64] = g_zs[cj * 64 + (tid - 64)];
    __syncthreads();

    int il = tid & 63;
    float2 a = zi[il];
    int j0 = tid >> 6;
    bool nondiag = (ci != cj);
    float acc = 0.f;
    #pragma unroll
    for (int kk = 0; kk < 16; kk++) {
        int jl = j0 + (kk << 2);
        float2 b = zj[jl];
        float dx = a.x - b.x, dy = a.y - b.y;
        float s = fmaf(dx, dx, dy * dy);
        float v = phi_sel(s, K1);
        acc += (nondiag | (jl > il)) ? v : 0.f;
    }
    acc = wsum(acc);
    if ((tid & 31) == 0) sRed[tid >> 5] = (double)acc;
    __syncthreads();
    if (tid == 0) {
        double s = 0;
        for (int i = 0; i < 8; i++) s += sRed[i];
        atomicAdd(&g_acc[0], s);
    }
}

// ---------------- finalize ----------------
__global__ void k_final(const float* __restrict__ means, const float* __restrict__ vars,
                        const float* __restrict__ probs, float* __restrict__ out,
                        float K1, double phi0, double scaleA, double gammaD)
{
    __shared__ double sC[4];
    int tid = threadIdx.x;
    double c = 0.0;
    if (tid < 100) {
        int i = tid / 10, j = tid % 10;
        float dx = means[2 * i] - means[2 * j];
        float dy = means[2 * i + 1] - means[2 * j + 1];
        float c1 = dx * dx + dy * dy;
        float vm = vars[i] + vars[j];
        float g = (float)gammaD;
        float x = c1 / (2.f * vm + 4.f * g);
        float c2 = phi_sel(x, K1);
        float c3 = probs[i] * probs[j] * rsqrtf(2.f * (float)M_PI * (vm + 2.f * g));
        c = (double)(c3 * c2);
    }
    // reduce 128 threads (4 warps)
    #pragma unroll
    for (int o = 16; o; o >>= 1) c += __shfl_xor_sync(FULLMASK, c, o);
    if ((tid & 31) == 0) sC[tid >> 5] = c;
    __syncthreads();
    if (tid == 0) {
        double C = sC[0] + sC[1] + sC[2] + sC[3];
        double A = (2.0 * g_acc[0] + (double)MROWS * phi0) * scaleA;
        double B = g_acc[4];
        double rec = g_acc[1] / ((double)MROWS * 64.0);
        double den = g_acc[3]; if (den == 0.0) den = 1.0;
        double cls = g_acc[2] / den;
        double cw = A - B + C;
        out[0] = (float)(rec + 8.0 + log(cw) + 2.0 * cls);
    }
}

extern "C" void kernel_launch(void* const* d_in, const int* in_sizes, int n_in,
                              void* d_out, int out_size) {
    const float* bd   = (const float*)d_in[0];
    const float* We1  = (const float*)d_in[1];
    const float* be1  = (const float*)d_in[2];
    const float* We2  = (const float*)d_in[3];
    const float* be2  = (const float*)d_in[4];
    const float* We3  = (const float*)d_in[5];
    const float* be3  = (const float*)d_in[6];
    const float* Wd1  = (const float*)d_in[7];
    const float* bd1  = (const float*)d_in[8];
    const float* Wd2  = (const float*)d_in[9];
    const float* bd2  = (const float*)d_in[10];
    const float* Wd3  = (const float*)d_in[11];
    const float* bd3  = (const float*)d_in[12];
    const float* means = (const float*)d_in[13];
    const float* vars  = (const float*)d_in[14];
    const float* probs = (const float*)d_in[15];
    float* out = (float*)d_out;

    const double m = (double)MROWS;
    const double gamma = pow(4.0 / (3.0 * m), 0.2);
    const double pf75 = exp(-3.75) * (1.0 + 3.5156229 + 3.0899424 + 1.2067492 +
                                      0.2659732 + 0.0360768 + 0.0045813);
    const double pg75 = sqrt(2.0 / 7.5) * (0.39894228 + 0.01328592 + 0.00225319 -
                                           0.00157565 + 0.0091628 - 0.02057706 +
                                           0.02635537 - 0.01647633 + 0.00392377);
    const double K1 = pg75 - pf75;
    const double phi0 = 1.0 + K1;
    const double scaleA = 1.0 / (m * m * sqrt(2.0 * M_PI * 2.0 * gamma));
    const float rsc = (float)(1.0 / sqrt(4.0 * gamma));
    const float K1f = (float)K1;
    const float gamf = (float)gamma;

    k_zero<<<1, 32>>>();
    k_rows<<<128, 256>>>(bd, We1, be1, We2, be2, We3, be3,
                         Wd1, bd1, Wd2, bd2, Wd3, bd3,
                         means, vars, probs, K1f, rsc, gamf);
    k_pairs<<<2080, 256>>>(K1f);
    k_final<<<1, 128>>>(means, vars, probs, out, K1f, phi0, scaleA, gamma);
}